// round 11
// baseline (speedup 1.0000x reference)
#include <cuda_runtime.h>
#include <cuda_bf16.h>

#define B_TOT 8192
#define T_LEN 60

typedef unsigned long long ull;

// global scratch: r1 (then overwritten by r2) in [t][j][b] layout
__device__ float g_r1[(size_t)T_LEN * 64 * B_TOT];

__device__ __forceinline__ void fma2(ull &d, ull a, ull b) {
    asm("fma.rn.f32x2 %0, %1, %2, %0;" : "+l"(d) : "l"(a), "l"(b));
}
__device__ __forceinline__ ull pk2(float x, float y) {
    ull r; asm("mov.b64 %0, {%1, %2};" : "=l"(r) : "f"(x), "f"(y)); return r;
}
__device__ __forceinline__ float2 unpk(ull v) {
    float2 f; asm("mov.b64 {%0, %1}, %2;" : "=f"(f.x), "=f"(f.y) : "l"(v)); return f;
}
__device__ __forceinline__ float redu(ull v) { float2 f = unpk(v); return f.x + f.y; }
__device__ __forceinline__ float tanha(float x) {
    float r; asm("tanh.approx.f32 %0, %1;" : "=f"(r) : "f"(x)); return r;
}
__device__ __forceinline__ float sigm(float x) {
    return fmaf(tanha(x * 0.5f), 0.5f, 0.5f);
}

// One LSTM layer, 64 hidden, 64 batches per block (grid 128), 512 threads.
// f32x2 packs TWO CONSECUTIVE K contributions of the same gate cell (no operand
// duplication). Acts stored as k-pair ull [KP][AST2]; weights as interleaved
// k-pair ull rows. Gate split: wg0 = gates i,f; wg1 = gates g,o (owns c,h).
// Lane = hidden-pair a (j = 2a, 2a+1); warp-in-wg wb = batches 8wb..8wb+7.
template<int KIN>
__global__ void __launch_bounds__(512, 1) lstm_kernel(
    const float* __restrict__ inputs_main,
    const float* __restrict__ inputs_aux,
    const float* __restrict__ rnn1_mem,
    const float* __restrict__ Wi, const float* __restrict__ bi,
    const float* __restrict__ Whx1, const float* __restrict__ bhx1,  // Ws1/bs1 | Wt1/bt1
    const float* __restrict__ Whx2, const float* __restrict__ bhx2,  // Ws2/bs2 | Wt2/bt2
    const float* __restrict__ Wih, const float* __restrict__ Whh,
    const float* __restrict__ bih, const float* __restrict__ bhh,
    const float* __restrict__ Wso, const float* __restrict__ bso,
    float* __restrict__ out_sfc)
{
    constexpr bool IS1 = (KIN == 80);
    constexpr int KTOT = KIN + 64;
    constexpr int KP   = KTOT / 2;   // k-pairs
    constexpr int KINP = KIN / 2;    // input k-pairs
    constexpr int AST2 = 66;         // act2 row stride in ull (EVEN: keeps 16B alignment)
    constexpr int SB   = 33;         // sbuf row stride in float4

    extern __shared__ char smem_raw[];
    ull*    wA2   = (ull*)smem_raw;                  // [KP][128]: wg0 (i,f) k-pair weights
    ull*    wB2   = wA2 + KP * 128;                  // wg1 (g,o)
    ull*    act2  = wB2 + KP * 128;                  // [KP][AST2] k-pair activations
    float4* sbuf  = (float4*)(act2 + KP * AST2);     // [64 b][SB]: (si0, sf0, si1, sf1)
    ull*    sbias = (ull*)(sbuf + 64 * SB);          // [256]: pk2(bias, 0) per (wg,pairsel,a,jj)
    float*  sWi   = (float*)(sbias + 256);           // 256 (LSTM1)
    float*  sbi   = sWi + 256;                       // 64  (LSTM1)

    const int tid  = threadIdx.x;
    const int lane = tid & 31;          // hidden-pair a
    const int wb   = (tid >> 5) & 7;    // batch group within wg
    const int wg   = tid >> 8;          // 0: i,f   1: g,o
    const int b0   = blockIdx.x * 64;

    // ---- stage weights as k-pairs, interleaved for dense LDS.128:
    // (half h, kp) row of 128 ull: [pairsel(0=X,1=Y)*64 + a*2 + jj]
    //   X gate = (h?g:i), Y gate = (h?o:f); j = 2a+jj; value = pk2(W[row][2kp], W[row][2kp+1])
    for (int idx = tid; idx < KP * 256; idx += 512) {
        int kp = idx >> 8, r = idx & 255;
        int half = r >> 7, e = r & 127;
        int pairsel = e >> 6, a = (e >> 1) & 31, jj = e & 1;
        int row = (2 * half + pairsel) * 64 + 2 * a + jj;
        int c0 = 2 * kp, c1 = 2 * kp + 1;
        float w0 = (c0 < KIN) ? Wih[row * KIN + c0] : Whh[row * 64 + (c0 - KIN)];
        float w1 = (c1 < KIN) ? Wih[row * KIN + c1] : Whh[row * 64 + (c1 - KIN)];
        (half ? wB2 : wA2)[kp * 128 + e] = pk2(w0, w1);
    }
    if (tid < 256) {
        int half = tid >> 7, e = tid & 127;
        int pairsel = e >> 6, a = (e >> 1) & 31, jj = e & 1;
        int g = 2 * half + pairsel;
        int j = 2 * a + jj;
        sbias[tid] = pk2(bih[g * 64 + j] + bhh[g * 64 + j], 0.0f);
    }
    if (IS1) {
        if (tid < 256) sWi[tid] = Wi[tid];
        if (tid < 64)  sbi[tid] = bi[tid];
    }

    // ---- initial h0 (k-pair rows of act2) and c0 (registers, wg1 only)
    float cst[8][2];
    if (wg == 1) {
        #pragma unroll
        for (int b = 0; b < 8; b++) {
            const int bb = b0 + 8 * wb + b;
            float h0[2];
            #pragma unroll
            for (int e = 0; e < 2; e++) {
                const int j = 2 * lane + e;
                float hh, cc;
                if (IS1) {
                    float a0 = inputs_aux[bb * 3 + 0], a1 = inputs_aux[bb * 3 + 1], a2 = inputs_aux[bb * 3 + 2];
                    hh = tanha(a0 * Whx1[j * 3 + 0] + a1 * Whx1[j * 3 + 1] + a2 * Whx1[j * 3 + 2] + bhx1[j]);
                    cc = tanha(a0 * Whx2[j * 3 + 0] + a1 * Whx2[j * 3 + 1] + a2 * Whx2[j * 3 + 2] + bhx2[j]);
                } else {
                    float toa = inputs_aux[bb * 3 + 1];
                    hh = toa * Whx1[j] + bhx1[j];
                    cc = toa * Whx2[j] + bhx2[j];
                }
                h0[e] = hh;
                cst[b][e] = cc;
            }
            act2[(KINP + lane) * AST2 + 8 * wb + b] = pk2(h0[0], h0[1]);
        }
    }
    __syncthreads();  // weights/sWi/sbias visible

    // ---- phase A for the first step (wg0 threads)
    const int bA = tid & 63, kq = (tid >> 6) & 3;
    if (wg == 0) {
        const int tf = IS1 ? (T_LEN - 1) : 0;
        if (IS1) {
            const float4 mv = *(const float4*)(inputs_main + ((size_t)(b0 + bA) * T_LEN + tf) * 4);
            #pragma unroll
            for (int kk = 0; kk < 8; kk++) {
                int k = kq * 16 + 2 * kk;
                float v0 = tanha(mv.x * sWi[k * 4]     + mv.y * sWi[k * 4 + 1] +
                                 mv.z * sWi[k * 4 + 2] + mv.w * sWi[k * 4 + 3] + sbi[k]);
                float v1 = tanha(mv.x * sWi[k * 4 + 4] + mv.y * sWi[k * 4 + 5] +
                                 mv.z * sWi[k * 4 + 6] + mv.w * sWi[k * 4 + 7] + sbi[k + 1]);
                act2[(kq * 8 + kk) * AST2 + bA] = pk2(v0, v1);
            }
            const float4 mm = *(const float4*)(rnn1_mem + (((size_t)(b0 + bA) * T_LEN + tf) * 16 + kq * 4));
            act2[(32 + kq * 2 + 0) * AST2 + bA] = pk2(mm.x, mm.y);
            act2[(32 + kq * 2 + 1) * AST2 + bA] = pk2(mm.z, mm.w);
        } else {
            #pragma unroll
            for (int m = 0; m < 8; m++) {
                int j = kq * 16 + 2 * m;
                float v0 = g_r1[((size_t)0 * 64 + j) * B_TOT + b0 + bA];
                float v1 = g_r1[((size_t)0 * 64 + j + 1) * B_TOT + b0 + bA];
                act2[(kq * 8 + m) * AST2 + bA] = pk2(v0, v1);
            }
        }
    }
    __syncthreads();

    const ull* wp = (wg ? wB2 : wA2) + lane * 2;
    const ull* ap = act2 + 8 * wb;
    const ulonglong2 bX = *(const ulonglong2*)(sbias + wg * 128 + lane * 2);       // (X j0, X j1)
    const ulonglong2 bY = *(const ulonglong2*)(sbias + wg * 128 + 64 + lane * 2);  // (Y j0, Y j1)

    // ---- time loop
    for (int s = 0; s < T_LEN; s++) {
        const int t = IS1 ? (T_LEN - 1 - s) : s;

        ull aX0[8], aX1[8], aY0[8], aY1[8];
        #pragma unroll
        for (int b = 0; b < 8; b++) { aX0[b] = bX.x; aX1[b] = bX.y; aY0[b] = bY.x; aY1[b] = bY.y; }

        #pragma unroll 2
        for (int kp = 0; kp < KP; kp++) {
            ulonglong2 wX = *(const ulonglong2*)(wp + kp * 128);        // (X j0, X j1) k-pair
            ulonglong2 wY = *(const ulonglong2*)(wp + kp * 128 + 64);   // (Y j0, Y j1) k-pair
            ulonglong2 x01 = *(const ulonglong2*)(ap + kp * AST2);      // batches +0,+1 (uniform)
            ulonglong2 x23 = *(const ulonglong2*)(ap + kp * AST2 + 2);
            ulonglong2 x45 = *(const ulonglong2*)(ap + kp * AST2 + 4);
            ulonglong2 x67 = *(const ulonglong2*)(ap + kp * AST2 + 6);
            ull xv[8] = {x01.x, x01.y, x23.x, x23.y, x45.x, x45.y, x67.x, x67.y};
            #pragma unroll
            for (int b = 0; b < 8; b++) {
                fma2(aX0[b], wX.x, xv[b]);
                fma2(aX1[b], wX.y, xv[b]);
                fma2(aY0[b], wY.x, xv[b]);
                fma2(aY1[b], wY.y, xv[b]);
            }
        }

        const bool havenext = (s < T_LEN - 1);
        const int t2 = IS1 ? (t - 1) : (t + 1);
        float4 mv, mm;
        float rv0[8], rv1[8];
        float tg0[8], tg1[8], so0[8], so1[8];

        if (wg == 0) {
            // prefetch next-step inputs (consumed after the sync)
            if (havenext) {
                if (IS1) {
                    mv = *(const float4*)(inputs_main + ((size_t)(b0 + bA) * T_LEN + t2) * 4);
                    mm = *(const float4*)(rnn1_mem + (((size_t)(b0 + bA) * T_LEN + t2) * 16 + kq * 4));
                } else {
                    #pragma unroll
                    for (int m = 0; m < 8; m++) {
                        int j = kq * 16 + 2 * m;
                        rv0[m] = g_r1[((size_t)t2 * 64 + j) * B_TOT + b0 + bA];
                        rv1[m] = g_r1[((size_t)t2 * 64 + j + 1) * B_TOT + b0 + bA];
                    }
                }
            }
            // sigmoid(i), sigmoid(f) -> sbuf
            #pragma unroll
            for (int b = 0; b < 8; b++) {
                sbuf[(8 * wb + b) * SB + lane] =
                    make_float4(sigm(redu(aX0[b])), sigm(redu(aY0[b])),
                                sigm(redu(aX1[b])), sigm(redu(aY1[b])));
            }
        } else {
            // hoisted: tanh(g), sigmoid(o) — independent of sbuf
            #pragma unroll
            for (int b = 0; b < 8; b++) {
                tg0[b] = tanha(redu(aX0[b]));
                tg1[b] = tanha(redu(aX1[b]));
                so0[b] = sigm(redu(aY0[b]));
                so1[b] = sigm(redu(aY1[b]));
            }
        }
        __syncthreads();

        if (wg == 1) {
            // combine: c' = sf*c + si*tg; h = so*tanh(c')
            float h0[8], h1[8];
            #pragma unroll
            for (int b = 0; b < 8; b++) {
                float4 sg = sbuf[(8 * wb + b) * SB + lane];  // (si0, sf0, si1, sf1)
                float c0 = sg.y * cst[b][0] + sg.x * tg0[b];
                cst[b][0] = c0;
                h0[b] = so0[b] * tanha(c0);
                float c1 = sg.w * cst[b][1] + sg.z * tg1[b];
                cst[b][1] = c1;
                h1[b] = so1[b] * tanha(c1);
            }
            // h -> act2 k-pair rows (8 contiguous ull = 4 STS.128)
            ull* hp = act2 + (KINP + lane) * AST2 + 8 * wb;
            *(ulonglong2*)(hp + 0) = make_ulonglong2(pk2(h0[0], h1[0]), pk2(h0[1], h1[1]));
            *(ulonglong2*)(hp + 2) = make_ulonglong2(pk2(h0[2], h1[2]), pk2(h0[3], h1[3]));
            *(ulonglong2*)(hp + 4) = make_ulonglong2(pk2(h0[4], h1[4]), pk2(h0[5], h1[5]));
            *(ulonglong2*)(hp + 6) = make_ulonglong2(pk2(h0[6], h1[6]), pk2(h0[7], h1[7]));
            // h -> transposed global (r1 / r2)
            const int j0 = 2 * lane;
            float* gp0 = g_r1 + ((size_t)t * 64 + j0) * B_TOT + b0 + 8 * wb;
            float* gp1 = g_r1 + ((size_t)t * 64 + j0 + 1) * B_TOT + b0 + 8 * wb;
            *(float4*)(gp0)     = make_float4(h0[0], h0[1], h0[2], h0[3]);
            *(float4*)(gp0 + 4) = make_float4(h0[4], h0[5], h0[6], h0[7]);
            *(float4*)(gp1)     = make_float4(h1[0], h1[1], h1[2], h1[3]);
            *(float4*)(gp1 + 4) = make_float4(h1[4], h1[5], h1[6], h1[7]);
        } else if (havenext) {
            // phase A: fill input k-pair rows for next step
            if (IS1) {
                #pragma unroll
                for (int kk = 0; kk < 8; kk++) {
                    int k = kq * 16 + 2 * kk;
                    float v0 = tanha(mv.x * sWi[k * 4]     + mv.y * sWi[k * 4 + 1] +
                                     mv.z * sWi[k * 4 + 2] + mv.w * sWi[k * 4 + 3] + sbi[k]);
                    float v1 = tanha(mv.x * sWi[k * 4 + 4] + mv.y * sWi[k * 4 + 5] +
                                     mv.z * sWi[k * 4 + 6] + mv.w * sWi[k * 4 + 7] + sbi[k + 1]);
                    act2[(kq * 8 + kk) * AST2 + bA] = pk2(v0, v1);
                }
                act2[(32 + kq * 2 + 0) * AST2 + bA] = pk2(mm.x, mm.y);
                act2[(32 + kq * 2 + 1) * AST2 + bA] = pk2(mm.z, mm.w);
            } else {
                #pragma unroll
                for (int m = 0; m < 8; m++)
                    act2[(kq * 8 + m) * AST2 + bA] = pk2(rv0[m], rv1[m]);
            }
        }
        __syncthreads();
    }

    // ---- out_sfc = hL @ Wso^T + bso (LSTM2 only; final h in act2 recurrent rows)
    if (!IS1) {
        if (tid < 64) {
            float s0 = bso[0], s1 = bso[1], s2 = bso[2];
            #pragma unroll 8
            for (int a = 0; a < 32; a++) {
                float2 h = unpk(act2[(KINP + a) * AST2 + tid]);
                s0 += Wso[0 * 64 + 2 * a] * h.x + Wso[0 * 64 + 2 * a + 1] * h.y;
                s1 += Wso[1 * 64 + 2 * a] * h.x + Wso[1 * 64 + 2 * a + 1] * h.y;
                s2 += Wso[2 * 64 + 2 * a] * h.x + Wso[2 * 64 + 2 * a + 1] * h.y;
            }
            out_sfc[(size_t)(b0 + tid) * 3 + 0] = s0;
            out_sfc[(size_t)(b0 + tid) * 3 + 1] = s1;
            out_sfc[(size_t)(b0 + tid) * 3 + 2] = s2;
        }
    }
}

// lat = r2 @ Wl^T + bl ; new_mem = lat ; out = lat @ Wo^T + bo
__global__ void __launch_bounds__(256) head_kernel(
    const float* __restrict__ Wl, const float* __restrict__ bl,
    const float* __restrict__ Wo, const float* __restrict__ bo,
    float* __restrict__ out, float* __restrict__ newmem)
{
    __shared__ float sWl[1024], sbl[16], sWo[64], sbo[4];
    const int tid = threadIdx.x;
    for (int i = tid; i < 1024; i += 256) sWl[i] = Wl[i];
    if (tid < 16) sbl[tid] = bl[tid];
    if (tid < 64) sWo[tid] = Wo[tid];
    if (tid < 4)  sbo[tid] = bo[tid];
    __syncthreads();

    const int t = blockIdx.x;
    const size_t b = (size_t)blockIdx.y * 256 + tid;

    float lat[16];
    #pragma unroll
    for (int m = 0; m < 16; m++) lat[m] = sbl[m];

    #pragma unroll
    for (int c = 0; c < 4; c++) {
        float v[16];
        #pragma unroll
        for (int jj = 0; jj < 16; jj++)
            v[jj] = g_r1[((size_t)t * 64 + c * 16 + jj) * B_TOT + b];
        #pragma unroll
        for (int m = 0; m < 16; m++) {
            float s = lat[m];
            #pragma unroll
            for (int jj = 0; jj < 16; jj++)
                s += sWl[m * 64 + c * 16 + jj] * v[jj];
            lat[m] = s;
        }
    }

    float4* nm = (float4*)(newmem + (b * T_LEN + t) * 16);
    nm[0] = make_float4(lat[0], lat[1], lat[2], lat[3]);
    nm[1] = make_float4(lat[4], lat[5], lat[6], lat[7]);
    nm[2] = make_float4(lat[8], lat[9], lat[10], lat[11]);
    nm[3] = make_float4(lat[12], lat[13], lat[14], lat[15]);

    float o[4];
    #pragma unroll
    for (int y = 0; y < 4; y++) {
        float s = sbo[y];
        #pragma unroll
        for (int m = 0; m < 16; m++) s += sWo[y * 16 + m] * lat[m];
        o[y] = s;
    }
    *(float4*)(out + (b * T_LEN + t) * 4) = make_float4(o[0], o[1], o[2], o[3]);
}

extern "C" void kernel_launch(void* const* d_in, const int* in_sizes, int n_in,
                              void* d_out, int out_size) {
    const float* inputs_main = (const float*)d_in[0];
    const float* inputs_aux  = (const float*)d_in[1];
    const float* rnn1_mem    = (const float*)d_in[2];
    const float* Wi   = (const float*)d_in[3];
    const float* bi   = (const float*)d_in[4];
    const float* Ws1  = (const float*)d_in[5];
    const float* bs1  = (const float*)d_in[6];
    const float* Ws2  = (const float*)d_in[7];
    const float* bs2  = (const float*)d_in[8];
    const float* Wt1  = (const float*)d_in[9];
    const float* bt1  = (const float*)d_in[10];
    const float* Wt2  = (const float*)d_in[11];
    const float* bt2  = (const float*)d_in[12];
    const float* Wih1 = (const float*)d_in[13];
    const float* Whh1 = (const float*)d_in[14];
    const float* bih1 = (const float*)d_in[15];
    const float* bhh1 = (const float*)d_in[16];
    const float* Wih2 = (const float*)d_in[17];
    const float* Whh2 = (const float*)d_in[18];
    const float* bih2 = (const float*)d_in[19];
    const float* bhh2 = (const float*)d_in[20];
    const float* Wl   = (const float*)d_in[21];
    const float* bl   = (const float*)d_in[22];
    const float* Wo   = (const float*)d_in[23];
    const float* bo   = (const float*)d_in[24];
    const float* Wso  = (const float*)d_in[25];
    const float* bso  = (const float*)d_in[26];

    float* out     = (float*)d_out;
    float* out_sfc = out + (size_t)B_TOT * T_LEN * 4;
    float* newmem  = out_sfc + (size_t)B_TOT * 3;

    // smem: weights(k-pair) + act2(k-pair) + sbuf + sbias + sWi/sbi
    const int smem1 = 72 * 128 * 8 * 2 + 72 * 66 * 8 + 64 * 33 * 16 + 256 * 8 + (256 + 64) * 4;
    const int smem2 = 64 * 128 * 8 * 2 + 64 * 66 * 8 + 64 * 33 * 16 + 256 * 8 + (256 + 64) * 4;
    cudaFuncSetAttribute((const void*)lstm_kernel<80>, cudaFuncAttributeMaxDynamicSharedMemorySize, smem1);
    cudaFuncSetAttribute((const void*)lstm_kernel<64>, cudaFuncAttributeMaxDynamicSharedMemorySize, smem2);

    lstm_kernel<80><<<128, 512, smem1>>>(inputs_main, inputs_aux, rnn1_mem, Wi, bi,
                                         Ws1, bs1, Ws2, bs2, Wih1, Whh1, bih1, bhh1,
                                         nullptr, nullptr, nullptr);
    lstm_kernel<64><<<128, 512, smem2>>>(inputs_main, inputs_aux, rnn1_mem, Wi, bi,
                                         Wt1, bt1, Wt2, bt2, Wih2, Whh2, bih2, bhh2,
                                         Wso, bso, out_sfc);
    head_kernel<<<dim3(T_LEN, B_TOT / 256), 256>>>(Wl, bl, Wo, bo, out, newmem);
}

// round 17
// speedup vs baseline: 1.2212x; 1.2212x over previous
#include <cuda_runtime.h>
#include <cuda_fp16.h>

#define B_TOT 8192
#define T_LEN 60
typedef unsigned int u32;
typedef unsigned long long ull;

// r1 (then r2) in [t][j][b] layout
__device__ float g_r1[(size_t)T_LEN * 64 * B_TOT];
// Gx: per-layer x-part gate preacts (+bias), [t][gate g][j-pair a][b] as float2=(j=2a, j=2a+1)
__device__ float2 g_gx[(size_t)T_LEN * 4 * 32 * B_TOT];

__device__ __forceinline__ float tanha(float x){float r;asm("tanh.approx.f32 %0, %1;":"=f"(r):"f"(x));return r;}
__device__ __forceinline__ float sigm(float x){return fmaf(tanha(x*0.5f),0.5f,0.5f);}
__device__ __forceinline__ void hsplit(float v,float&hi,float&lo){hi=__half2float(__float2half_rn(v));lo=v-hi;}
__device__ __forceinline__ u32 hpair(float a,float b){__half2 t;t.x=__float2half_rn(a);t.y=__float2half_rn(b);return *(u32*)&t;}
__device__ __forceinline__ void fma2(ull &d, ull a, ull b) {
    asm("fma.rn.f32x2 %0, %1, %2, %0;" : "+l"(d) : "l"(a), "l"(b));
}
__device__ __forceinline__ float2 unpk(ull v) {
    float2 f; asm("mov.b64 {%0, %1}, %2;" : "=f"(f.x), "=f"(f.y) : "l"(v)); return f;
}
__device__ __forceinline__ ull dup2(float x) {
    ull r; asm("mov.b64 %0, {%1, %1};" : "=l"(r) : "f"(x)); return r;
}

__device__ __forceinline__ void mma16816(float* c, const uint4& a, u32 b0, u32 b1) {
    asm volatile(
        "mma.sync.aligned.m16n8k16.row.col.f32.f16.f16.f32 "
        "{%0,%1,%2,%3}, {%4,%5,%6,%7}, {%8,%9}, {%0,%1,%2,%3};"
        : "+f"(c[0]), "+f"(c[1]), "+f"(c[2]), "+f"(c[3])
        : "r"(a.x), "r"(a.y), "r"(a.z), "r"(a.w), "r"(b0), "r"(b1));
}

// ---------------------------------------------------------------------------
// gx_mma<KIN>: time-parallel x-part gate GEMM on tensor cores.
// Gx[t][n] = W_ih[n,:] . x_t + (bih+bhh)[n], for all t, n = g*64+j.
// Fragment layouts and thread mapping identical to the mapping-verified R13/R14
// kernel. fp16 hi/lo, 3 chained passes. Grid 128 x 64 batches, 256 threads.
// KIN=80: x = [tanh(Wi*main+bi), mem]; KIN=64: x = r1 (from g_r1).
// ---------------------------------------------------------------------------
template<int KIN>
__global__ void __launch_bounds__(256, 1) gx_mma(
    const float* __restrict__ inputs_main, const float* __restrict__ rnn1_mem,
    const float* __restrict__ Wi, const float* __restrict__ bi,
    const float* __restrict__ Wih,
    const float* __restrict__ bih, const float* __restrict__ bhh)
{
    constexpr bool IS1 = (KIN == 80);
    constexpr int NCH  = KIN / 16;
    constexpr int NBW  = NCH * 16 * 32 * 4;  // u32 slots per weight version
    constexpr int NAW  = NCH * 4 * 32 * 4;   // u32 slots per act version
    constexpr int NKP  = KIN / 2;
    constexpr int KPT  = NKP / 4;            // k-pairs per staging group

    extern __shared__ char smem_raw[];
    float* sb   = (float*)smem_raw;            // 256 biases (natural n)
    float* sWi  = (float*)(smem_raw + 1024);
    float* sbi  = (float*)(smem_raw + 2048);
    u32* BhiU = (u32*)(smem_raw + 4096);
    u32* BloU = BhiU + NBW;
    u32* AhiU = BloU + NBW;
    u32* AloU = AhiU + NAW;
    const uint4* Bhi4 = (const uint4*)BhiU;
    const uint4* Blo4 = (const uint4*)BloU;
    const uint4* Ahi4 = (const uint4*)AhiU;
    const uint4* Alo4 = (const uint4*)AloU;

    const int tid  = threadIdx.x;
    const int lane = tid & 31;
    const int wid  = tid >> 5;
    const int Ms   = wid & 1;
    const int ns   = wid >> 1;
    const int b0   = blockIdx.x * 64;
    const int tg   = lane & 3;
    const int lr   = lane >> 2;

    // weight fragments (hi/lo fp16), layout as verified
    for (int idx = tid; idx < NBW; idx += 256) {
        int c  = idx >> 11;
        int np = (idx >> 7) & 15;
        int l  = (idx >> 2) & 31;
        int q  = (idx >> 1) & 1;
        int rg = idx & 1;
        int n  = (np * 2 + q) * 8 + (l >> 2);
        int kb = c * 16 + (l & 3) * 2 + rg * 8;
        float v0 = Wih[n * KIN + kb];
        float v1 = Wih[n * KIN + kb + 1];
        float h0, l0, h1, l1; hsplit(v0, h0, l0); hsplit(v1, h1, l1);
        BhiU[idx] = hpair(h0, h1);
        BloU[idx] = hpair(l0, l1);
    }
    if (tid < 256) sb[tid] = bih[tid] + bhh[tid];
    if (IS1) {
        if (tid < 256) sWi[tid] = Wi[tid];
        if (tid < 64)  sbi[tid] = bi[tid];
    }

    auto stage_x = [&](int tt) {
        const int row = tid & 63, grp = tid >> 6;
        const int bb = b0 + row;
        const int m = row >> 4;
        float4 mv;
        if (IS1) mv = *(const float4*)(inputs_main + ((size_t)bb * T_LEN + tt) * 4);
        #pragma unroll
        for (int i = 0; i < KPT; i++) {
            int kp = grp * KPT + i;
            float v0, v1;
            if (IS1) {
                int k0 = 2 * kp;
                if (k0 < 64) {
                    v0 = tanha(mv.x * sWi[k0 * 4 + 0] + mv.y * sWi[k0 * 4 + 1] +
                               mv.z * sWi[k0 * 4 + 2] + mv.w * sWi[k0 * 4 + 3] + sbi[k0]);
                    v1 = tanha(mv.x * sWi[k0 * 4 + 4] + mv.y * sWi[k0 * 4 + 5] +
                               mv.z * sWi[k0 * 4 + 6] + mv.w * sWi[k0 * 4 + 7] + sbi[k0 + 1]);
                } else {
                    float2 mp = *(const float2*)(rnn1_mem + ((size_t)bb * T_LEN + tt) * 16 + (k0 - 64));
                    v0 = mp.x; v1 = mp.y;
                }
            } else {
                v0 = g_r1[((size_t)tt * 64 + 2 * kp)     * B_TOT + bb];
                v1 = g_r1[((size_t)tt * 64 + 2 * kp + 1) * B_TOT + bb];
            }
            int c = kp >> 3;
            int lanep = ((row & 7) << 2) | (kp & 3);
            int slot = ((c * 4 + m) * 32 + lanep) * 4 + ((kp >> 2) & 1) * 2 + ((row >> 3) & 1);
            float h0, l0, h1, l1; hsplit(v0, h0, l0); hsplit(v1, h1, l1);
            AhiU[slot] = hpair(h0, h1);
            AloU[slot] = hpair(l0, l1);
        }
    };

    __syncthreads();   // sWi/sbi ready for stage_x
    stage_x(0);
    __syncthreads();

    for (int t = 0; t < T_LEN; t++) {
        float acc[2][4][2][4];
        #pragma unroll
        for (int mt = 0; mt < 2; mt++)
        #pragma unroll
        for (int g = 0; g < 4; g++)
        #pragma unroll
        for (int q = 0; q < 2; q++)
        #pragma unroll
        for (int x = 0; x < 4; x++) acc[mt][g][q][x] = 0.0f;

        #pragma unroll
        for (int c = 0; c < NCH; c++) {
            uint4 ah0 = Ahi4[(c * 4 + 2 * Ms + 0) * 32 + lane];
            uint4 ah1 = Ahi4[(c * 4 + 2 * Ms + 1) * 32 + lane];
            uint4 al0 = Alo4[(c * 4 + 2 * Ms + 0) * 32 + lane];
            uint4 al1 = Alo4[(c * 4 + 2 * Ms + 1) * 32 + lane];
            #pragma unroll
            for (int g = 0; g < 4; g++) {
                uint4 bh = Bhi4[(c * 16 + 4 * g + ns) * 32 + lane];
                uint4 bl = Blo4[(c * 16 + 4 * g + ns) * 32 + lane];
                mma16816(acc[0][g][0], ah0, bh.x, bh.y);
                mma16816(acc[0][g][1], ah0, bh.z, bh.w);
                mma16816(acc[1][g][0], ah1, bh.x, bh.y);
                mma16816(acc[1][g][1], ah1, bh.z, bh.w);
                mma16816(acc[0][g][0], al0, bh.x, bh.y);
                mma16816(acc[0][g][1], al0, bh.z, bh.w);
                mma16816(acc[1][g][0], al1, bh.x, bh.y);
                mma16816(acc[1][g][1], al1, bh.z, bh.w);
                mma16816(acc[0][g][0], ah0, bl.x, bl.y);
                mma16816(acc[0][g][1], ah0, bl.z, bl.w);
                mma16816(acc[1][g][0], ah1, bl.x, bl.y);
                mma16816(acc[1][g][1], ah1, bl.z, bl.w);
            }
        }
        __syncthreads();  // done reading A frags

        // write Gx + bias; thread owns (4 batches x 4 j x 4 gates)
        #pragma unroll
        for (int mt = 0; mt < 2; mt++)
        #pragma unroll
        for (int q = 0; q < 2; q++) {
            const int j0 = 16 * ns + 8 * q + 2 * tg;
            const int a  = j0 >> 1;
            #pragma unroll
            for (int g = 0; g < 4; g++) {
                float bv0 = sb[g * 64 + j0], bv1 = sb[g * 64 + j0 + 1];
                #pragma unroll
                for (int rsel = 0; rsel < 2; rsel++) {
                    int row = 32 * Ms + 16 * mt + 8 * rsel + lr;
                    float2 v = make_float2(acc[mt][g][q][2 * rsel + 0] + bv0,
                                           acc[mt][g][q][2 * rsel + 1] + bv1);
                    g_gx[((size_t)(t * 4 + g) * 32 + a) * B_TOT + b0 + row] = v;
                }
            }
        }

        if (t < T_LEN - 1) stage_x(t + 1);
        __syncthreads();
    }
}

// ---------------------------------------------------------------------------
// lstm_serial<IS1>: recurrent-only fp32 SIMT kernel (K = 64 h-rows only).
// Structure = proven R6 kernel; Gx (x-part + bias) read from g_gx in epilogue.
// Grid 128 x 64 batches, 512 threads; wg0 = gates i,f; wg1 = g,o (owns c,h).
// ---------------------------------------------------------------------------
template<bool IS1>
__global__ void __launch_bounds__(512, 1) lstm_serial(
    const float* __restrict__ inputs_aux,
    const float* __restrict__ Whx1, const float* __restrict__ bhx1,
    const float* __restrict__ Whx2, const float* __restrict__ bhx2,
    const float* __restrict__ Whh)
{
    constexpr int AST = 68;
    constexpr int SB  = 33;

    extern __shared__ char smem_raw[];
    float*  wAf  = (float*)smem_raw;            // [64][128]: per pair a: i0,i1,f0,f1
    float*  wBf  = wAf + 64 * 128;              // g0,g1,o0,o1
    float*  act  = wBf + 64 * 128;              // [64][AST] h rows
    float4* sbuf = (float4*)(act + 64 * AST);   // [64 b][SB]

    const int tid  = threadIdx.x;
    const int lane = tid & 31;          // hidden-pair a (j = 2a, 2a+1)
    const int wb   = (tid >> 5) & 7;    // batches 8wb..8wb+7
    const int wg   = tid >> 8;          // 0: i,f   1: g,o
    const int b0   = blockIdx.x * 64;

    for (int idx = tid; idx < 64 * 256; idx += 512) {
        int k = idx >> 8, r = idx & 255;
        int half = r >> 7, rr = r & 127;
        int p = rr >> 2, q = rr & 3;
        int row = half * 128 + (q >> 1) * 64 + 2 * p + (q & 1);
        (half ? wBf : wAf)[k * 128 + rr] = Whh[row * 64 + k];
    }

    float cst[8][2];
    if (wg == 1) {
        #pragma unroll
        for (int e = 0; e < 2; e++) {
            const int j = 2 * lane + e;
            #pragma unroll
            for (int b = 0; b < 8; b++) {
                const int bb = b0 + 8 * wb + b;
                float h0, c0;
                if (IS1) {
                    float a0 = inputs_aux[bb * 3 + 0], a1 = inputs_aux[bb * 3 + 1], a2 = inputs_aux[bb * 3 + 2];
                    h0 = tanha(a0 * Whx1[j * 3 + 0] + a1 * Whx1[j * 3 + 1] + a2 * Whx1[j * 3 + 2] + bhx1[j]);
                    c0 = tanha(a0 * Whx2[j * 3 + 0] + a1 * Whx2[j * 3 + 1] + a2 * Whx2[j * 3 + 2] + bhx2[j]);
                } else {
                    float toa = inputs_aux[bb * 3 + 1];
                    h0 = toa * Whx1[j] + bhx1[j];
                    c0 = toa * Whx2[j] + bhx2[j];
                }
                cst[b][e] = c0;
                act[j * AST + 8 * wb + b] = h0;
            }
        }
    }
    __syncthreads();

    const float* wp = (wg ? wBf : wAf) + lane * 4;
    const float* ap = act + 8 * wb;

    for (int s = 0; s < T_LEN; s++) {
        const int t = IS1 ? (T_LEN - 1 - s) : s;

        ull aX[8], aY[8];
        #pragma unroll
        for (int b = 0; b < 8; b++) { aX[b] = 0ULL; aY[b] = 0ULL; }

        #pragma unroll 4
        for (int k = 0; k < 64; k++) {
            ulonglong2 wv = *(const ulonglong2*)(wp + k * 128);   // .x = gateX pair, .y = gateY pair
            float4 x0 = *(const float4*)(ap + k * AST);
            float4 x1 = *(const float4*)(ap + k * AST + 4);
            ull d[8];
            d[0] = dup2(x0.x); d[1] = dup2(x0.y); d[2] = dup2(x0.z); d[3] = dup2(x0.w);
            d[4] = dup2(x1.x); d[5] = dup2(x1.y); d[6] = dup2(x1.z); d[7] = dup2(x1.w);
            #pragma unroll
            for (int b = 0; b < 8; b++) {
                fma2(aX[b], wv.x, d[b]);
                fma2(aY[b], wv.y, d[b]);
            }
        }

        // Gx loads (x-part + bias, fp32, coalesced; latency hidden by epilogue)
        const float2* gxXp = g_gx + ((size_t)(t * 4 + 2 * wg + 0) * 32 + lane) * B_TOT + b0 + 8 * wb;
        const float2* gxYp = g_gx + ((size_t)(t * 4 + 2 * wg + 1) * 32 + lane) * B_TOT + b0 + 8 * wb;
        float4 gx0 = *(const float4*)(gxXp + 0);
        float4 gx1 = *(const float4*)(gxXp + 2);
        float4 gx2 = *(const float4*)(gxXp + 4);
        float4 gx3 = *(const float4*)(gxXp + 6);
        float4 gy0 = *(const float4*)(gxYp + 0);
        float4 gy1 = *(const float4*)(gxYp + 2);
        float4 gy2 = *(const float4*)(gxYp + 4);
        float4 gy3 = *(const float4*)(gxYp + 6);
        float2 gX[8] = {make_float2(gx0.x,gx0.y), make_float2(gx0.z,gx0.w),
                        make_float2(gx1.x,gx1.y), make_float2(gx1.z,gx1.w),
                        make_float2(gx2.x,gx2.y), make_float2(gx2.z,gx2.w),
                        make_float2(gx3.x,gx3.y), make_float2(gx3.z,gx3.w)};
        float2 gY[8] = {make_float2(gy0.x,gy0.y), make_float2(gy0.z,gy0.w),
                        make_float2(gy1.x,gy1.y), make_float2(gy1.z,gy1.w),
                        make_float2(gy2.x,gy2.y), make_float2(gy2.z,gy2.w),
                        make_float2(gy3.x,gy3.y), make_float2(gy3.z,gy3.w)};

        float tg0[8], tg1[8], so0[8], so1[8];
        if (wg == 0) {
            #pragma unroll
            for (int b = 0; b < 8; b++) {
                float2 gi = unpk(aX[b]);
                float2 gf = unpk(aY[b]);
                sbuf[(8 * wb + b) * SB + lane] =
                    make_float4(sigm(gi.x + gX[b].x), sigm(gf.x + gY[b].x),
                                sigm(gi.y + gX[b].y), sigm(gf.y + gY[b].y));
            }
        } else {
            #pragma unroll
            for (int b = 0; b < 8; b++) {
                float2 gg = unpk(aX[b]);
                float2 go = unpk(aY[b]);
                tg0[b] = tanha(gg.x + gX[b].x);
                tg1[b] = tanha(gg.y + gX[b].y);
                so0[b] = sigm(go.x + gY[b].x);
                so1[b] = sigm(go.y + gY[b].y);
            }
        }
        __syncthreads();

        if (wg == 1) {
            float h0[8], h1[8];
            #pragma unroll
            for (int b = 0; b < 8; b++) {
                float4 sg = sbuf[(8 * wb + b) * SB + lane];  // (si0, sf0, si1, sf1)
                float c0 = sg.y * cst[b][0] + sg.x * tg0[b];
                cst[b][0] = c0;
                h0[b] = so0[b] * tanha(c0);
                float c1 = sg.w * cst[b][1] + sg.z * tg1[b];
                cst[b][1] = c1;
                h1[b] = so1[b] * tanha(c1);
            }
            const int j0 = 2 * lane;
            *(float4*)(act + j0 * AST + 8 * wb)           = make_float4(h0[0], h0[1], h0[2], h0[3]);
            *(float4*)(act + j0 * AST + 8 * wb + 4)       = make_float4(h0[4], h0[5], h0[6], h0[7]);
            *(float4*)(act + (j0 + 1) * AST + 8 * wb)     = make_float4(h1[0], h1[1], h1[2], h1[3]);
            *(float4*)(act + (j0 + 1) * AST + 8 * wb + 4) = make_float4(h1[4], h1[5], h1[6], h1[7]);
            float* gp0 = g_r1 + ((size_t)t * 64 + j0) * B_TOT + b0 + 8 * wb;
            float* gp1 = g_r1 + ((size_t)t * 64 + j0 + 1) * B_TOT + b0 + 8 * wb;
            *(float4*)(gp0)     = make_float4(h0[0], h0[1], h0[2], h0[3]);
            *(float4*)(gp0 + 4) = make_float4(h0[4], h0[5], h0[6], h0[7]);
            *(float4*)(gp1)     = make_float4(h1[0], h1[1], h1[2], h1[3]);
            *(float4*)(gp1 + 4) = make_float4(h1[4], h1[5], h1[6], h1[7]);
        }
        __syncthreads();
    }
}

// lat = r2 @ Wl^T + bl ; new_mem = lat ; out = lat @ Wo^T + bo
__global__ void __launch_bounds__(256) head_kernel(
    const float* __restrict__ Wl, const float* __restrict__ bl,
    const float* __restrict__ Wo, const float* __restrict__ bo,
    float* __restrict__ out, float* __restrict__ newmem)
{
    __shared__ float sWl[1024], sbl[16], sWo[64], sbo[4];
    const int tid = threadIdx.x;
    for (int i = tid; i < 1024; i += 256) sWl[i] = Wl[i];
    if (tid < 16) sbl[tid] = bl[tid];
    if (tid < 64) sWo[tid] = Wo[tid];
    if (tid < 4)  sbo[tid] = bo[tid];
    __syncthreads();

    const int t = blockIdx.x;
    const size_t b = (size_t)blockIdx.y * 256 + tid;

    float lat[16];
    #pragma unroll
    for (int m = 0; m < 16; m++) lat[m] = sbl[m];
    #pragma unroll
    for (int c = 0; c < 4; c++) {
        float v[16];
        #pragma unroll
        for (int jj = 0; jj < 16; jj++)
            v[jj] = g_r1[((size_t)t * 64 + c * 16 + jj) * B_TOT + b];
        #pragma unroll
        for (int m = 0; m < 16; m++) {
            float s = lat[m];
            #pragma unroll
            for (int jj = 0; jj < 16; jj++)
                s += sWl[m * 64 + c * 16 + jj] * v[jj];
            lat[m] = s;
        }
    }

    float4* nm = (float4*)(newmem + (b * T_LEN + t) * 16);
    nm[0] = make_float4(lat[0], lat[1], lat[2], lat[3]);
    nm[1] = make_float4(lat[4], lat[5], lat[6], lat[7]);
    nm[2] = make_float4(lat[8], lat[9], lat[10], lat[11]);
    nm[3] = make_float4(lat[12], lat[13], lat[14], lat[15]);

    float o[4];
    #pragma unroll
    for (int y = 0; y < 4; y++) {
        float s = sbo[y];
        #pragma unroll
        for (int m = 0; m < 16; m++) s += sWo[y * 16 + m] * lat[m];
        o[y] = s;
    }
    *(float4*)(out + (b * T_LEN + t) * 4) = make_float4(o[0], o[1], o[2], o[3]);
}

// out_sfc = hL @ Wso^T + bso ; hL = r2[:, T-1] in g_r1
__global__ void __launch_bounds__(256) sfc_kernel(
    const float* __restrict__ Wso, const float* __restrict__ bso,
    float* __restrict__ out_sfc)
{
    const size_t b = (size_t)blockIdx.x * 256 + threadIdx.x;
    float s0 = bso[0], s1 = bso[1], s2 = bso[2];
    #pragma unroll 8
    for (int j = 0; j < 64; j++) {
        float h = g_r1[((size_t)(T_LEN - 1) * 64 + j) * B_TOT + b];
        s0 += Wso[j] * h;
        s1 += Wso[64 + j] * h;
        s2 += Wso[128 + j] * h;
    }
    out_sfc[b * 3 + 0] = s0;
    out_sfc[b * 3 + 1] = s1;
    out_sfc[b * 3 + 2] = s2;
}

extern "C" void kernel_launch(void* const* d_in, const int* in_sizes, int n_in,
                              void* d_out, int out_size) {
    const float* inputs_main = (const float*)d_in[0];
    const float* inputs_aux  = (const float*)d_in[1];
    const float* rnn1_mem    = (const float*)d_in[2];
    const float* Wi   = (const float*)d_in[3];
    const float* bi   = (const float*)d_in[4];
    const float* Ws1  = (const float*)d_in[5];
    const float* bs1  = (const float*)d_in[6];
    const float* Ws2  = (const float*)d_in[7];
    const float* bs2  = (const float*)d_in[8];
    const float* Wt1  = (const float*)d_in[9];
    const float* bt1  = (const float*)d_in[10];
    const float* Wt2  = (const float*)d_in[11];
    const float* bt2  = (const float*)d_in[12];
    const float* Wih1 = (const float*)d_in[13];
    const float* Whh1 = (const float*)d_in[14];
    const float* bih1 = (const float*)d_in[15];
    const float* bhh1 = (const float*)d_in[16];
    const float* Wih2 = (const float*)d_in[17];
    const float* Whh2 = (const float*)d_in[18];
    const float* bih2 = (const float*)d_in[19];
    const float* bhh2 = (const float*)d_in[20];
    const float* Wl   = (const float*)d_in[21];
    const float* bl   = (const float*)d_in[22];
    const float* Wo   = (const float*)d_in[23];
    const float* bo   = (const float*)d_in[24];
    const float* Wso  = (const float*)d_in[25];
    const float* bso  = (const float*)d_in[26];

    float* out     = (float*)d_out;
    float* out_sfc = out + (size_t)B_TOT * T_LEN * 4;
    float* newmem  = out_sfc + (size_t)B_TOT * 3;

    // gx smem: 4KB header + 2*B-frags + 2*A-frags
    const int smem_g1 = 4096 + 2 * (5 * 16 * 32 * 16) + 2 * (5 * 4 * 32 * 16);  // 106496
    const int smem_g2 = 4096 + 2 * (4 * 16 * 32 * 16) + 2 * (4 * 4 * 32 * 16);  // 86016
    // serial smem: weights + act + sbuf
    const int smem_s  = 64 * 256 * 4 + 64 * 68 * 4 + 64 * 33 * 16;              // 116736
    cudaFuncSetAttribute((const void*)gx_mma<80>, cudaFuncAttributeMaxDynamicSharedMemorySize, smem_g1);
    cudaFuncSetAttribute((const void*)gx_mma<64>, cudaFuncAttributeMaxDynamicSharedMemorySize, smem_g2);
    cudaFuncSetAttribute((const void*)lstm_serial<true>,  cudaFuncAttributeMaxDynamicSharedMemorySize, smem_s);
    cudaFuncSetAttribute((const void*)lstm_serial<false>, cudaFuncAttributeMaxDynamicSharedMemorySize, smem_s);

    // LSTM1: x-part GEMM (time-parallel, TC) then fp32 recurrence
    gx_mma<80><<<128, 256, smem_g1>>>(inputs_main, rnn1_mem, Wi, bi, Wih1, bih1, bhh1);
    lstm_serial<true><<<128, 512, smem_s>>>(inputs_aux, Ws1, bs1, Ws2, bs2, Whh1);
    // LSTM2: x-part = Wih2 . r1 (r1 now complete in g_r1), then recurrence
    gx_mma<64><<<128, 256, smem_g2>>>(inputs_main, rnn1_mem, Wi, bi, Wih2, bih2, bhh2);
    lstm_serial<false><<<128, 512, smem_s>>>(inputs_aux, Wt1, bt1, Wt2, bt2, Whh2);

    head_kernel<<<dim3(T_LEN, B_TOT / 256), 256>>>(Wl, bl, Wo, bo, out, newmem);
    sfc_kernel<<<B_TOT / 256, 256>>>(Wso, bso, out_sfc);
}